// round 6
// baseline (speedup 1.0000x reference)
#include <cuda_runtime.h>
#include <math.h>

// ---------------- problem constants ----------------
#define TT 512
#define BB 64
#define II 256
#define HH 1024
#define AA 128
#define OO 1024
#define PSZ0 13568   // I + 13H
#define PSZ1 14336   // H + 13O
#define NB 256       // persistent CTAs (co-resident: 2/SM on >=128 SMs)
#define BIGB (1 << 30)

// ---------------- device scratch (static, no runtime alloc) ----------------
__device__ float g_part[16 * 64 * 4096];   // split-K partials (max: S6 = 16 x 64 x 4096)
__device__ float g_ahe [BB * PSZ1];        // policy output (reused L0/L1)
__device__ float g_a0x[BB * AA];
__device__ float g_a0c[BB * AA];
__device__ float g_a1x[BB * AA];
__device__ float g_a1c[BB * AA];
__device__ float g_f0x[BB * HH];
__device__ float g_f0c[BB * HH];
__device__ float g_f1x[BB * OO];
__device__ float g_f1c[BB * OO];
__device__ unsigned g_cnt = 0;
__device__ unsigned g_gen = 0;

__device__ __forceinline__ float sigf(float x) { return 1.0f / (1.0f + __expf(-x)); }

// ---------------- grid-wide barrier (persistent kernel) ----------------
__device__ __forceinline__ void gsync() {
    __syncthreads();
    if (threadIdx.x == 0) {
        unsigned gen = *(volatile unsigned*)&g_gen;
        __threadfence();                        // release: make my writes visible
        if (atomicInc(&g_cnt, NB - 1) == NB - 1) {
            atomicAdd(&g_gen, 1);
        } else {
            while (*(volatile unsigned*)&g_gen == gen) { __nanosleep(32); }
        }
        __threadfence();                        // acquire: invalidate L1 (CCTL.IVALL)
    }
    __syncthreads();
}

// ---------------- GEMM stage ----------------
// C[64 x N] = A[64 x K] @ W[N x K]^T, tiled 64 x TN, K chunked (KCH in {32,128}).
// A = virtual concat of up to 4 sources (boundaries b0<b1<b2, chunk-aligned).
// Optional elementwise A-scale: A[b][k] *= scale[b*sstr + k] (k = concat index).
// W = virtual concat of 2 sources split at wsplit.
// bias != null (single-chunk): final C+bias -> outF. Else partial -> outP[kc].
// Thread map: tm = tid>>5 (warp id, 8 rows each), tn = lane (TN/32 cols each).
// smem: sA[64][33] (row-major, broadcast reads), sW[32][TN+4] (k-major, vector reads).
template<int TN>
__device__ void gemm_stage(
    float* sA, float* sW,
    int nunits, int ntiles, int KCH,
    const float* __restrict__ A0, const float* __restrict__ A1,
    const float* __restrict__ A2, const float* __restrict__ A3,
    int s0, int s1, int s2, int s3, int b0, int b1, int b2,
    const float* __restrict__ scale, int sstr,
    const float* __restrict__ W0, int w0s,
    const float* __restrict__ W1, int w1s, int wsplit,
    const float* __restrict__ bias,
    float* __restrict__ outP, float* __restrict__ outF, int N)
{
    constexpr int MN = TN / 32;       // 4 or 2
    constexpr int WPAD = TN + 4;
    const int tid = threadIdx.x;
    const int tm = tid >> 5;          // 0..7 (warp id)
    const int tn = tid & 31;          // lane

    for (int u = blockIdx.x; u < nunits; u += NB) {
        const int ntile = u % ntiles;
        const int kc    = u / ntiles;
        const int kbase = kc * KCH;

        const float* Asrc; int Astr, aloc;
        if      (kbase < b0) { Asrc = A0; Astr = s0; aloc = kbase;      }
        else if (kbase < b1) { Asrc = A1; Astr = s1; aloc = kbase - b0; }
        else if (kbase < b2) { Asrc = A2; Astr = s2; aloc = kbase - b1; }
        else                 { Asrc = A3; Astr = s3; aloc = kbase - b2; }
        const float* Wsrc; int Wstr, wloc;
        if (kbase < wsplit) { Wsrc = W0; Wstr = w0s; wloc = kbase; }
        else                { Wsrc = W1; Wstr = w1s; wloc = kbase - wsplit; }

        float acc[8][MN];
#pragma unroll
        for (int i = 0; i < 8; i++)
#pragma unroll
            for (int j = 0; j < MN; j++) acc[i][j] = 0.0f;

        for (int k0 = 0; k0 < KCH; k0 += 32) {
            __syncthreads();
            // stage A: 64 x 32, coalesced on k, row-major in smem
#pragma unroll
            for (int i = 0; i < 8; i++) {
                int e = i * 256 + tid;
                int k = e & 31, b = e >> 5;
                float v = Asrc[b * Astr + aloc + k0 + k];
                if (scale) v *= scale[b * sstr + kbase + k0 + k];
                sA[b * 33 + k] = v;
            }
            // stage W: TN x 32, coalesced on k, TRANSPOSED (k-major) in smem
#pragma unroll
            for (int i = 0; i < TN / 8; i++) {
                int e = i * 256 + tid;
                int k = e & 31, n = e >> 5;
                sW[k * WPAD + n] = Wsrc[(size_t)(ntile * TN + n) * Wstr + wloc + k0 + k];
            }
            __syncthreads();
#pragma unroll
            for (int k = 0; k < 32; k++) {
                float w[MN];
                if (MN == 4) {
                    float4 wv = *(const float4*)(sW + k * WPAD + tn * 4);
                    w[0] = wv.x; w[1] = wv.y; w[2] = wv.z; w[3] = wv.w;
                } else {
                    float2 wv = *(const float2*)(sW + k * WPAD + tn * 2);
                    w[0] = wv.x; w[1] = wv.y;
                }
#pragma unroll
                for (int i = 0; i < 8; i++) {
                    float a = sA[(tm * 8 + i) * 33 + k];   // warp-broadcast
#pragma unroll
                    for (int j = 0; j < MN; j++) acc[i][j] += a * w[j];
                }
            }
        }

        const int col = ntile * TN + tn * MN;
        if (bias) {
#pragma unroll
            for (int i = 0; i < 8; i++) {
                int r = tm * 8 + i;
#pragma unroll
                for (int j = 0; j < MN; j++)
                    outF[(size_t)r * N + col + j] = acc[i][j] + bias[col + j];
            }
        } else {
            float* dst = outP + (size_t)kc * 64 * N;
#pragma unroll
            for (int i = 0; i < 8; i++) {
                int r = tm * 8 + i;
                if (MN == 4) {
                    float4 v; v.x = acc[i][0]; v.y = acc[i][1]; v.z = acc[i][2]; v.w = acc[i][3];
                    *(float4*)(dst + (size_t)r * N + col) = v;
                } else {
                    float2 v; v.x = acc[i][0]; v.y = acc[i][1];
                    *(float2*)(dst + (size_t)r * N + col) = v;
                }
            }
        }
    }
}

// ---------------- adapt (plain LSTM) cell finalize ----------------
__device__ void adapt_cell(const float* __restrict__ part, int nch,
                           const float* __restrict__ bih, const float* __restrict__ bhh,
                           float* __restrict__ xs, float* __restrict__ cs)
{
    int idx = blockIdx.x * 256 + threadIdx.x;
    if (idx < BB * AA) {
        int b = idx >> 7, a = idx & 127;
        const float* p = part + b * 512 + a;
        float g0 = bih[a]       + bhh[a];
        float g1 = bih[128 + a] + bhh[128 + a];
        float g2 = bih[256 + a] + bhh[256 + a];
        float g3 = bih[384 + a] + bhh[384 + a];
        for (int kc = 0; kc < nch; kc++, p += 64 * 512) {
            g0 += p[0]; g1 += p[128]; g2 += p[256]; g3 += p[384];
        }
        float i = sigf(g0), f = sigf(g1), gg = tanhf(g2), o = sigf(g3);
        float c2 = f * cs[idx] + i * gg;
        cs[idx] = c2;
        xs[idx] = o * tanhf(c2);
    }
}

// ---------------- adaptive (f) cell finalize ----------------
__device__ void fcell_cell(const float* __restrict__ part, int nx, int ntot,
                           const float* __restrict__ fb, const float* __restrict__ ahe,
                           int psz, int ninp,
                           float* __restrict__ xs, float* __restrict__ cs,
                           float* __restrict__ out)
{
    int idx = blockIdx.x * 256 + threadIdx.x;   // exactly 65536 = 64*1024
    int b = idx >> 10, h = idx & 1023;
    const float* ab = ahe + (size_t)b * psz;
    float g[4];
#pragma unroll
    for (int q = 0; q < 4; q++) {
        int n = (q << 10) + h;
        const float* p = part + b * 4096 + n;
        float px = 0.0f, ph = 0.0f;
        int kc = 0;
        for (; kc < nx; kc++)   px += p[kc * (64 * 4096)];
        for (; kc < ntot; kc++) ph += p[kc * (64 * 4096)];
        g[q] = px * ab[ninp + 1024 + n] + ph * ab[ninp + 5120 + n]
             + fb[n] * ab[ninp + 9216 + n];
    }
    float i = sigf(g[0]), f = sigf(g[1]), gg = tanhf(g[2]), o = sigf(g[3]);
    float c2 = f * cs[idx] + i * gg;
    float hx = o * tanhf(c2);
    cs[idx] = c2;
    xs[idx] = hx;
    if (out) out[idx] = hx;
}

// ---------------- persistent kernel ----------------
__global__ void __launch_bounds__(256, 2) alstm_persist(
    const float* __restrict__ x,
    const float* __restrict__ a_wih0, const float* __restrict__ a_whh0,
    const float* __restrict__ a_bih0, const float* __restrict__ a_bhh0,
    const float* __restrict__ p_w0,   const float* __restrict__ p_b0,
    const float* __restrict__ f_wih0, const float* __restrict__ f_whh0,
    const float* __restrict__ f_b0,
    const float* __restrict__ a_wih1, const float* __restrict__ a_whh1,
    const float* __restrict__ a_bih1, const float* __restrict__ a_bhh1,
    const float* __restrict__ p_w1,   const float* __restrict__ p_b1,
    const float* __restrict__ f_wih1, const float* __restrict__ f_whh1,
    const float* __restrict__ f_b1,
    float* __restrict__ out)
{
    __shared__ __align__(16) float sA[64 * 33];
    __shared__ __align__(16) float sW[32 * 132];

    const int gtid = blockIdx.x * 256 + threadIdx.x;

    // zero initial states
    for (int i = gtid; i < BB * AA; i += NB * 256) {
        g_a0x[i] = 0.0f; g_a0c[i] = 0.0f; g_a1x[i] = 0.0f; g_a1c[i] = 0.0f;
    }
    for (int i = gtid; i < BB * HH; i += NB * 256) {
        g_f0x[i] = 0.0f; g_f0c[i] = 0.0f; g_f1x[i] = 0.0f; g_f1c[i] = 0.0f;
    }
    gsync();

    for (int t = 0; t < TT; t++) {
        const float* xt = x + (size_t)t * BB * II;

        // S1: adapt0 GEMM. A = [xt(256)|f0x(1024)|a1x(128)|a0x(128)], K=1536, N=512
        gemm_stage<128>(sA, sW, 192, 4, 32,
            xt, g_f0x, g_a1x, g_a0x, II, HH, AA, AA, 256, 1280, 1408,
            nullptr, 0,
            a_wih0, 1408, a_whh0, 128, 1408,
            nullptr, g_part, nullptr, 512);
        gsync();
        adapt_cell(g_part, 48, a_bih0, a_bhh0, g_a0x, g_a0c);
        gsync();

        // S2: ahe0 = a0x @ p_w0^T + p_b0 (K=128 full, N=13568)
        gemm_stage<64>(sA, sW, PSZ0 / 64, PSZ0 / 64, 128,
            g_a0x, g_a0x, g_a0x, g_a0x, AA, AA, AA, AA, BIGB, BIGB, BIGB,
            nullptr, 0,
            p_w0, AA, p_w0, AA, BIGB,
            p_b0, nullptr, g_ahe, PSZ0);
        gsync();

        // S3: fcell0 GEMM. A = [xt*a_x(256)|f0x*a_h(1024)], N=4096
        gemm_stage<64>(sA, sW, 640, 64, 128,
            xt, g_f0x, g_f0x, g_f0x, II, HH, HH, HH, 256, BIGB, BIGB,
            g_ahe, PSZ0,
            f_wih0, II, f_whh0, HH, 256,
            nullptr, g_part, nullptr, 4096);
        gsync();
        fcell_cell(g_part, 2, 10, f_b0, g_ahe, PSZ0, II, g_f0x, g_f0c, nullptr);
        gsync();

        // S4: adapt1 GEMM. A = [f0x(1024)|f1x(1024)|a0x(128)|a1x(128)], K=2304, N=512
        gemm_stage<64>(sA, sW, 576, 8, 32,
            g_f0x, g_f1x, g_a0x, g_a1x, HH, OO, AA, AA, 1024, 2048, 2176,
            nullptr, 0,
            a_wih1, 2176, a_whh1, 128, 2176,
            nullptr, g_part, nullptr, 512);
        gsync();
        adapt_cell(g_part, 72, a_bih1, a_bhh1, g_a1x, g_a1c);
        gsync();

        // S5: ahe1 = a1x @ p_w1^T + p_b1 (K=128 full, N=14336)
        gemm_stage<64>(sA, sW, PSZ1 / 64, PSZ1 / 64, 128,
            g_a1x, g_a1x, g_a1x, g_a1x, AA, AA, AA, AA, BIGB, BIGB, BIGB,
            nullptr, 0,
            p_w1, AA, p_w1, AA, BIGB,
            p_b1, nullptr, g_ahe, PSZ1);
        gsync();

        // S6: fcell1 GEMM. A = [f0x*a_x(1024)|f1x*a_h(1024)], N=4096
        gemm_stage<128>(sA, sW, 512, 32, 128,
            g_f0x, g_f1x, g_f1x, g_f1x, HH, OO, OO, OO, 1024, BIGB, BIGB,
            g_ahe, PSZ1,
            f_wih1, HH, f_whh1, OO, 1024,
            nullptr, g_part, nullptr, 4096);
        gsync();
        fcell_cell(g_part, 8, 16, f_b1, g_ahe, PSZ1, HH, g_f1x, g_f1c,
                   out + (size_t)t * BB * OO);
        gsync();
    }
}

// ---------------- launcher: ONE graph node ----------------
extern "C" void kernel_launch(void* const* d_in, const int* in_sizes, int n_in,
                              void* d_out, int out_size)
{
    alstm_persist<<<NB, 256>>>(
        (const float*)d_in[0],
        (const float*)d_in[1],  (const float*)d_in[2],
        (const float*)d_in[3],  (const float*)d_in[4],
        (const float*)d_in[5],  (const float*)d_in[6],
        (const float*)d_in[7],  (const float*)d_in[8],
        (const float*)d_in[9],
        (const float*)d_in[10], (const float*)d_in[11],
        (const float*)d_in[12], (const float*)d_in[13],
        (const float*)d_in[14], (const float*)d_in[15],
        (const float*)d_in[16], (const float*)d_in[17],
        (const float*)d_in[18],
        (float*)d_out);
}